// round 15
// baseline (speedup 1.0000x reference)
#include <cuda_runtime.h>
#include <cuda_bf16.h>
#include <cstdint>

// Trajectory signature kernel, v9: persistent CTAs (grid 888 = 148*6),
// continuous cp.async tile stream across trajectories. Skeleton and
// compute body identical to v8 (3-buffer ring, depth-2, 512-row tiles,
// 1 LDS.64 + 4 conflict-free LDS.128 per thread).
// Input:  trajectories [4096, 2048, 6] fp32 (row-major)
// Output: [4096, 5] fp32

#define T_LEN   2048
#define N_TRAJ  4096
#define GRID    888                       // 148 SMs * 6 CTAs
#define TPT     4                         // tiles per trajectory
#define TILE    512
#define F4_PER_TRAJ (T_LEN * 6 / 4)       // 3072
#define F4_PER_TILE (TILE * 6 / 4)        // 768
#define HALO_W  8                         // halo row at words [2..7]
#define BUF_WORDS (HALO_W + TILE * 6)     // 3080 words
#define EPS_NORM 1e-6f
#define EPS_MEAN 1e-6f

__device__ __forceinline__ float warp_sum(float x) {
    #pragma unroll
    for (int o = 16; o > 0; o >>= 1)
        x += __shfl_down_sync(0xffffffffu, x, o);
    return x;
}

__device__ __forceinline__ unsigned int smem_u32(const void* p) {
    unsigned int a;
    asm("{ .reg .u64 t; cvta.to.shared.u64 t, %1; cvt.u32.u64 %0, t; }"
        : "=r"(a) : "l"(p));
    return a;
}

#define CP_ASYNC16(dst_u32, src_ptr) \
    asm volatile("cp.async.cg.shared.global [%0], [%1], 16;" \
                 :: "r"(dst_u32), "l"(src_ptr) : "memory")
#define CP_COMMIT() asm volatile("cp.async.commit_group;" ::: "memory")
#define CP_WAIT(n)  asm volatile("cp.async.wait_group %0;" :: "n"(n) : "memory")

__global__ __launch_bounds__(256, 6) void signature_kernel(
    const float4* __restrict__ trajv, float* __restrict__ out)
{
    __shared__ __align__(16) float sb[3][BUF_WORDS];
    __shared__ float red[8][8];

    const int tid = threadIdx.x;
    const int bid = blockIdx.x;

    // CTAs 0..543 process 5 trajectories, rest 4 (4096 = 888*4 + 544)
    const int ntr   = (bid < (N_TRAJ - GRID * 4)) ? 5 : 4;
    const int total = ntr * TPT;          // total tiles in this CTA's stream

    // per-buffer smem byte address of float4 slot `tid` (word HALO_W + 4*tid)
    unsigned int dstb[3];
    #pragma unroll
    for (int b = 0; b < 3; ++b)
        dstb[b] = smem_u32(&sb[b][HALO_W + 4 * tid]);

    // global float4 source for tile g of this CTA's stream
    auto tile_src = [&](int g) -> const float4* {
        const int j = g >> 2, t = g & 3;
        return trajv + (size_t)(bid + j * GRID) * F4_PER_TRAJ
                     + t * F4_PER_TILE + tid;
    };

    // prologue: issue stream tiles 0 and 1
    #pragma unroll
    for (int s = 0; s < 2; ++s) {
        const float4* src = tile_src(s);
        CP_ASYNC16(dstb[s],            src);
        CP_ASYNC16(dstb[s] + 256 * 16, src + 256);
        CP_ASYNC16(dstb[s] + 512 * 16, src + 512);
        CP_COMMIT();
    }

    float s_curv = 0.f, cnt = 0.f;
    float s_vd = 0.f, s_ad = 0.f;
    float s_sp = 0.f, s_sp2 = 0.f;
    float s_f  = 0.f, s_f2  = 0.f;

    #pragma unroll 1
    for (int j = 0; j < 5; ++j) {
        if (j >= ntr) break;

        #pragma unroll
        for (int t = 0; t < TPT; ++t) {
            const int g = j * TPT + t;

            if (g == total - 1) { CP_WAIT(0); } else { CP_WAIT(1); }
            __syncthreads();   // tile-g visible to all; buf (g+2)%3 free

            float* cbuf = sb[g % 3];

            // issue stream tile g+2 (may belong to the next trajectory)
            if (g + 2 < total) {
                const int nb = (g + 2) % 3;
                const float4* src = tile_src(g + 2);
                CP_ASYNC16(dstb[nb],            src);
                CP_ASYNC16(dstb[nb] + 256 * 16, src + 256);
                CP_ASYNC16(dstb[nb] + 512 * 16, src + 512);
                CP_COMMIT();
            }

            // halo for next tile of the SAME trajectory (t<3): copy last row
            if (t < TPT - 1 && tid < 6)
                sb[(g + 1) % 3][2 + tid] = cbuf[HALO_W + (TILE - 1) * 6 + tid];

            // ---- compute rows 2*tid, 2*tid+1 (v8 body) ----
            // LDS.64 @ 12t-6 (pp) + 4x LDS.128 @ slots 3t-1..3t+2 (CF)
            const float* bw = &cbuf[HALO_W + 12 * tid];
            const float2 pp = *reinterpret_cast<const float2*>(bw - 6);
            const float4 qa = *reinterpret_cast<const float4*>(bw - 4); // pv,pa
            const float4 q0 = *reinterpret_cast<const float4*>(bw);     // p0,v0
            const float4 q1 = *reinterpret_cast<const float4*>(bw + 4); // a0,p1
            const float4 q2 = *reinterpret_cast<const float4*>(bw + 8); // v1,a1

            const float2 pv = make_float2(qa.x, qa.y), pa = make_float2(qa.z, qa.w);
            const float2 p0 = make_float2(q0.x, q0.y), v0 = make_float2(q0.z, q0.w);
            const float2 a0 = make_float2(q1.x, q1.y), p1 = make_float2(q1.z, q1.w);
            const float2 v1 = make_float2(q2.x, q2.y), a1 = make_float2(q2.z, q2.w);

            const float sp0 = sqrtf(v0.x * v0.x + v0.y * v0.y);
            const float sp1 = sqrtf(v1.x * v1.x + v1.y * v1.y);
            const float fo0 = sqrtf(a0.x * a0.x + a0.y * a0.y);
            const float fo1 = sqrtf(a1.x * a1.x + a1.y * a1.y);
            s_sp  += sp0 + sp1;
            s_sp2 = fmaf(sp0, sp0, s_sp2); s_sp2 = fmaf(sp1, sp1, s_sp2);
            s_f   += fo0 + fo1;
            s_f2  = fmaf(fo0, fo0, s_f2);  s_f2  = fmaf(fo1, fo1, s_f2);

            const float nsq0 = p0.x * p0.x + p0.y * p0.y;
            const float nsq1 = p1.x * p1.x + p1.y * p1.y;

            // row1 <- row0 diffs (per-traj r odd >= 1 always)
            s_vd += fabsf(v1.x - v0.x) + fabsf(v1.y - v0.y);
            s_ad += fabsf(a1.x - a0.x) + fabsf(a1.y - a0.y);

            const bool nf = (t > 0) | (tid > 0);  // rows 0/1 of traj excluded
            if (nf) {
                s_vd += fabsf(v0.x - pv.x) + fabsf(v0.y - pv.y);
                s_ad += fabsf(a0.x - pa.x) + fabsf(a0.y - pa.y);

                const float nsqp = pp.x * pp.x + pp.y * pp.y;
                const float cr0  = pp.x * p0.y - pp.y * p0.x;
                const float pr0  = nsqp * nsq0;
                if (pr0 > EPS_NORM * EPS_NORM) {
                    s_curv = fmaf(fabsf(cr0), rsqrtf(pr0), s_curv);
                    cnt += 1.0f;
                }
                const float cr1 = p0.x * p1.y - p0.y * p1.x;
                const float pr1 = nsq0 * nsq1;
                if (pr1 > EPS_NORM * EPS_NORM) {
                    s_curv = fmaf(fabsf(cr1), rsqrtf(pr1), s_curv);
                    cnt += 1.0f;
                }
            }
        }

        // ---- per-trajectory reduction & output ----
        float r_curv = warp_sum(s_curv);
        float r_cnt  = warp_sum(cnt);
        float r_vd   = warp_sum(s_vd);
        float r_ad   = warp_sum(s_ad);
        float r_sp   = warp_sum(s_sp);
        float r_sp2  = warp_sum(s_sp2);
        float r_f    = warp_sum(s_f);
        float r_f2   = warp_sum(s_f2);

        const int lane = tid & 31;
        const int wid  = tid >> 5;
        if (lane == 0) {
            red[wid][0] = r_curv; red[wid][1] = r_cnt;
            red[wid][2] = r_vd;   red[wid][3] = r_ad;
            red[wid][4] = r_sp;   red[wid][5] = r_sp2;
            red[wid][6] = r_f;    red[wid][7] = r_f2;
        }
        __syncthreads();

        if (tid == 0) {
            float t_curv = 0.f, t_cnt = 0.f, t_vd = 0.f, t_ad = 0.f;
            float t_sp = 0.f, t_sp2 = 0.f, t_f = 0.f, t_f2 = 0.f;
            #pragma unroll
            for (int w = 0; w < 8; ++w) {
                t_curv += red[w][0]; t_cnt += red[w][1];
                t_vd   += red[w][2]; t_ad  += red[w][3];
                t_sp   += red[w][4]; t_sp2 += red[w][5];
                t_f    += red[w][6]; t_f2  += red[w][7];
            }

            const float path_curvature = (t_cnt > 0.f) ? (t_curv / t_cnt) : 0.f;

            const float denom = 2.0f * (float)(T_LEN - 1);
            const float velocity_smoothness = 1.0f / (1.0f + t_vd / denom);
            const float acceleration_jerk   = t_ad / denom;

            const float msp = t_sp / (float)T_LEN;
            float var_sp = t_sp2 / (float)T_LEN - msp * msp;
            if (var_sp < 0.f) var_sp = 0.f;
            const float movement_rhythm = sqrtf(var_sp) / (msp + EPS_MEAN);

            const float mf = t_f / (float)T_LEN;
            float var_f = t_f2 / (float)T_LEN - mf * mf;
            if (var_f < 0.f) var_f = 0.f;
            const float force_modulation = sqrtf(var_f) / (mf + EPS_MEAN);

            float* o = out + (size_t)(bid + j * GRID) * 5;
            o[0] = path_curvature;
            o[1] = velocity_smoothness;
            o[2] = acceleration_jerk;
            o[3] = movement_rhythm;
            o[4] = force_modulation;
        }
        __syncthreads();   // red safe for reuse; next traj tiles already in flight

        // reset accumulators for next trajectory
        s_curv = 0.f; cnt = 0.f; s_vd = 0.f; s_ad = 0.f;
        s_sp = 0.f; s_sp2 = 0.f; s_f = 0.f; s_f2 = 0.f;
    }
}

extern "C" void kernel_launch(void* const* d_in, const int* in_sizes, int n_in,
                              void* d_out, int out_size) {
    const float4* traj = (const float4*)d_in[0];
    float* out = (float*)d_out;
    signature_kernel<<<GRID, 256>>>(traj, out);
}

// round 17
// speedup vs baseline: 1.0957x; 1.0957x over previous
#include <cuda_runtime.h>
#include <cuda_bf16.h>
#include <cstdint>

// Trajectory signature kernel, v10 (re-bench; round 16 was an infra failure).
// v8 skeleton with per-thread cp.async replaced by ONE cp.async.bulk (TMA)
// per tile + mbarrier complete_tx. Removes ~2300 cyc/SMSP/tile of LDGSTS
// issue cost that co-saturated with DRAM. 3-buffer ring, depth-2, 512-row
// tiles, occ 6, compute body = v8.
// Input:  trajectories [4096, 2048, 6] fp32 (row-major)
// Output: [4096, 5] fp32

#define T_LEN   2048
#define N_TRAJ  4096
#define TILE    512
#define NT      (T_LEN / TILE)            // 4
#define TILE_BYTES (TILE * 6 * 4)         // 12288
#define HALO_W  8                         // halo row at words [2..7]
#define BUF_WORDS (HALO_W + TILE * 6)     // 3080 words
#define EPS_NORM 1e-6f
#define EPS_MEAN 1e-6f

__device__ __forceinline__ float warp_sum(float x) {
    #pragma unroll
    for (int o = 16; o > 0; o >>= 1)
        x += __shfl_down_sync(0xffffffffu, x, o);
    return x;
}

__device__ __forceinline__ unsigned int smem_u32(const void* p) {
    unsigned int a;
    asm("{ .reg .u64 t; cvta.to.shared.u64 t, %1; cvt.u32.u64 %0, t; }"
        : "=r"(a) : "l"(p));
    return a;
}

#define MBAR_INIT(mb, cnt) \
    asm volatile("mbarrier.init.shared.b64 [%0], %1;" :: "r"(mb), "r"(cnt) : "memory")
#define MBAR_EXPECT_TX(mb, bytes) \
    asm volatile("mbarrier.arrive.expect_tx.shared.b64 _, [%0], %1;" \
                 :: "r"(mb), "r"(bytes) : "memory")
#define BULK_G2S(dst, src, bytes, mb) \
    asm volatile("cp.async.bulk.shared::cta.global.mbarrier::complete_tx::bytes " \
                 "[%0], [%1], %2, [%3];" \
                 :: "r"(dst), "l"(src), "r"(bytes), "r"(mb) : "memory")
#define FENCE_PROXY_ASYNC() asm volatile("fence.proxy.async.shared::cta;" ::: "memory")

__device__ __forceinline__ void mbar_wait(unsigned int mb, unsigned int parity) {
    unsigned int done;
    asm volatile(
        "{\n\t.reg .pred p;\n\t"
        "mbarrier.try_wait.parity.acquire.cta.shared::cta.b64 p, [%1], %2;\n\t"
        "selp.b32 %0, 1, 0, p;\n\t}"
        : "=r"(done) : "r"(mb), "r"(parity) : "memory");
    if (!done) {
        asm volatile(
            "{\n\t.reg .pred P1;\n\t"
            "WAIT_LOOP_%=:\n\t"
            "mbarrier.try_wait.parity.acquire.cta.shared::cta.b64 P1, [%0], %1, 0x989680;\n\t"
            "@P1 bra.uni WAIT_DONE_%=;\n\t"
            "bra.uni WAIT_LOOP_%=;\n\t"
            "WAIT_DONE_%=:\n\t}"
            :: "r"(mb), "r"(parity) : "memory");
    }
}

__global__ __launch_bounds__(256, 6) void signature_kernel(
    const float* __restrict__ traj, float* __restrict__ out)
{
    __shared__ __align__(16) float sb[3][BUF_WORDS];
    __shared__ __align__(8) unsigned long long mbar[3];
    __shared__ float red[8][8];

    const int tid = threadIdx.x;
    const int tr  = blockIdx.x;
    const float* base = traj + (size_t)tr * (T_LEN * 6);

    unsigned int mb[3], dstb[3];
    #pragma unroll
    for (int b = 0; b < 3; ++b) {
        mb[b]   = smem_u32(&mbar[b]);
        dstb[b] = smem_u32(&sb[b][HALO_W]);
    }

    if (tid == 0) {
        #pragma unroll
        for (int b = 0; b < 3; ++b) MBAR_INIT(mb[b], 1);
        FENCE_PROXY_ASYNC();
    }
    __syncthreads();

    // prologue: issue tiles 0 and 1 (one bulk copy each)
    if (tid == 0) {
        #pragma unroll
        for (int t = 0; t < 2; ++t) {
            MBAR_EXPECT_TX(mb[t], TILE_BYTES);
            BULK_G2S(dstb[t], base + t * (TILE * 6), TILE_BYTES, mb[t]);
        }
    }

    float s_curv = 0.f, cnt = 0.f;
    float s_vd = 0.f, s_ad = 0.f;
    float s_sp = 0.f, s_sp2 = 0.f;
    float s_f  = 0.f, s_f2  = 0.f;

    #pragma unroll
    for (int t = 0; t < NT; ++t) {
        // all threads done reading buf (t+2)%3 (from iteration t-1)
        __syncthreads();

        // issue tile t+2 into buffer (t+2)%3 (single bulk, off critical path)
        if (t + 2 < NT && tid == 0) {
            const int nb = (t + 2) % 3;
            MBAR_EXPECT_TX(mb[nb], TILE_BYTES);
            BULK_G2S(dstb[nb], base + (t + 2) * (TILE * 6), TILE_BYTES, mb[nb]);
        }

        // wait for tile t's data (acquire orders the LDS reads below)
        mbar_wait(mb[t % 3], (unsigned)((t / 3) & 1));

        float* cbuf = sb[t % 3];

        // halo for tile t+1: copy last row of tile t into next buffer's halo
        if (t + 1 < NT && tid < 6)
            sb[(t + 1) % 3][2 + tid] = cbuf[HALO_W + (TILE - 1) * 6 + tid];

        // ---- compute rows 2*tid, 2*tid+1 (v8 body) ----
        // LDS.64 @ 12t-6 (pp) + 4x LDS.128 @ slots 3t-1..3t+2 (conflict-free)
        const float* bw = &cbuf[HALO_W + 12 * tid];
        const float2 pp = *reinterpret_cast<const float2*>(bw - 6);
        const float4 qa = *reinterpret_cast<const float4*>(bw - 4); // pv,pa
        const float4 q0 = *reinterpret_cast<const float4*>(bw);     // p0,v0
        const float4 q1 = *reinterpret_cast<const float4*>(bw + 4); // a0,p1
        const float4 q2 = *reinterpret_cast<const float4*>(bw + 8); // v1,a1

        const float2 pv = make_float2(qa.x, qa.y), pa = make_float2(qa.z, qa.w);
        const float2 p0 = make_float2(q0.x, q0.y), v0 = make_float2(q0.z, q0.w);
        const float2 a0 = make_float2(q1.x, q1.y), p1 = make_float2(q1.z, q1.w);
        const float2 v1 = make_float2(q2.x, q2.y), a1 = make_float2(q2.z, q2.w);

        // per-row moments (both rows, always valid)
        const float sp0 = sqrtf(v0.x * v0.x + v0.y * v0.y);
        const float sp1 = sqrtf(v1.x * v1.x + v1.y * v1.y);
        const float fo0 = sqrtf(a0.x * a0.x + a0.y * a0.y);
        const float fo1 = sqrtf(a1.x * a1.x + a1.y * a1.y);
        s_sp  += sp0 + sp1;
        s_sp2 = fmaf(sp0, sp0, s_sp2); s_sp2 = fmaf(sp1, sp1, s_sp2);
        s_f   += fo0 + fo1;
        s_f2  = fmaf(fo0, fo0, s_f2);  s_f2  = fmaf(fo1, fo1, s_f2);

        const float nsq0 = p0.x * p0.x + p0.y * p0.y;
        const float nsq1 = p1.x * p1.x + p1.y * p1.y;

        // row1 <- row0 diffs (global r = 512t+2*tid+1 >= 1 always)
        s_vd += fabsf(v1.x - v0.x) + fabsf(v1.y - v0.y);
        s_ad += fabsf(a1.x - a0.x) + fabsf(a1.y - a0.y);

        const bool nf = (t > 0) | (tid > 0);   // rows 0/1 of trajectory excluded
        if (nf) {
            // row0 <- prev diffs
            s_vd += fabsf(v0.x - pv.x) + fabsf(v0.y - pv.y);
            s_ad += fabsf(a0.x - pa.x) + fabsf(a0.y - pa.y);

            // curvature row0 (v1=prev pos delta, v2=row0 pos delta)
            const float nsqp = pp.x * pp.x + pp.y * pp.y;
            const float cr0  = pp.x * p0.y - pp.y * p0.x;
            const float pr0  = nsqp * nsq0;
            if (pr0 > EPS_NORM * EPS_NORM) {
                s_curv = fmaf(fabsf(cr0), rsqrtf(pr0), s_curv);
                cnt += 1.0f;
            }
            // curvature row1
            const float cr1 = p0.x * p1.y - p0.y * p1.x;
            const float pr1 = nsq0 * nsq1;
            if (pr1 > EPS_NORM * EPS_NORM) {
                s_curv = fmaf(fabsf(cr1), rsqrtf(pr1), s_curv);
                cnt += 1.0f;
            }
        }
    }

    // reductions
    s_curv = warp_sum(s_curv);
    cnt    = warp_sum(cnt);
    s_vd   = warp_sum(s_vd);
    s_ad   = warp_sum(s_ad);
    s_sp   = warp_sum(s_sp);
    s_sp2  = warp_sum(s_sp2);
    s_f    = warp_sum(s_f);
    s_f2   = warp_sum(s_f2);

    const int lane = tid & 31;
    const int wid  = tid >> 5;
    if (lane == 0) {
        red[wid][0] = s_curv; red[wid][1] = cnt;
        red[wid][2] = s_vd;   red[wid][3] = s_ad;
        red[wid][4] = s_sp;   red[wid][5] = s_sp2;
        red[wid][6] = s_f;    red[wid][7] = s_f2;
    }
    __syncthreads();

    if (tid == 0) {
        float t_curv = 0.f, t_cnt = 0.f, t_vd = 0.f, t_ad = 0.f;
        float t_sp = 0.f, t_sp2 = 0.f, t_f = 0.f, t_f2 = 0.f;
        #pragma unroll
        for (int w = 0; w < 8; ++w) {
            t_curv += red[w][0]; t_cnt += red[w][1];
            t_vd   += red[w][2]; t_ad  += red[w][3];
            t_sp   += red[w][4]; t_sp2 += red[w][5];
            t_f    += red[w][6]; t_f2  += red[w][7];
        }

        const float path_curvature = (t_cnt > 0.f) ? (t_curv / t_cnt) : 0.f;

        const float denom = 2.0f * (float)(T_LEN - 1);
        const float velocity_smoothness = 1.0f / (1.0f + t_vd / denom);
        const float acceleration_jerk   = t_ad / denom;

        const float msp = t_sp / (float)T_LEN;
        float var_sp = t_sp2 / (float)T_LEN - msp * msp;
        if (var_sp < 0.f) var_sp = 0.f;
        const float movement_rhythm = sqrtf(var_sp) / (msp + EPS_MEAN);

        const float mf = t_f / (float)T_LEN;
        float var_f = t_f2 / (float)T_LEN - mf * mf;
        if (var_f < 0.f) var_f = 0.f;
        const float force_modulation = sqrtf(var_f) / (mf + EPS_MEAN);

        float* o = out + tr * 5;
        o[0] = path_curvature;
        o[1] = velocity_smoothness;
        o[2] = acceleration_jerk;
        o[3] = movement_rhythm;
        o[4] = force_modulation;
    }
}

extern "C" void kernel_launch(void* const* d_in, const int* in_sizes, int n_in,
                              void* d_out, int out_size) {
    const float* traj = (const float*)d_in[0];
    float* out = (float*)d_out;
    signature_kernel<<<N_TRAJ, 256>>>(traj, out);
}